// round 1
// baseline (speedup 1.0000x reference)
#include <cuda_runtime.h>
#include <math.h>

// BayesRingRNN collapses exactly to a 2-scalar recurrence per batch because
// W_even/W_odd/M are rank-2 in {cos phi, sin phi} and r0 lies in that span.
// r_i(t) = u(t)*cos(phi_i) + v(t)*sin(phi_i).

#define NN 80
#define TT 1500

__global__ void __launch_bounds__(128, 8)
ring_kernel(const float* __restrict__ inputs,   // (B, T, 2)
            const float* __restrict__ phi,      // (N,)
            float* __restrict__ out,            // (B,T,N) then (B,N)
            int B, float kz, long long out_size)
{
    const int warp_global = (blockIdx.x * blockDim.x + threadIdx.x) >> 5;
    const int lane = threadIdx.x & 31;
    if (warp_global >= B) return;
    const int b = warp_global;

    // Per-lane neuron angles: neurons lane, lane+32, lane+64 (last only lane<16)
    float c0, s0, c1, s1, c2 = 0.f, s2 = 0.f;
    sincosf(phi[lane],      &s0, &c0);
    sincosf(phi[lane + 32], &s1, &c1);
    if (lane < NN - 64) sincosf(phi[lane + 64], &s2, &c2);

    // Constants (KP=1, KV=2, DT=0.01):
    // ALPHA*DT = DT/3 ; DT/(KP+KV) = DT/3 ; DT*a_even = DT/3 ; a_odd = 2/3
    const float C1 = 0.01f / 3.0f;          // sqrt-term coefficient
    const float C0 = 1.0f - 0.01f / 3.0f;   // 1 - ALPHA*DT
    const float C2 = 0.01f / 3.0f;          // DT * a_even
    const float C3 = 2.0f / 3.0f;           // a_odd

    float u = 10.0f;   // r0 = KAPPA_0 * cos(phi) -> u=10, v=0 exactly
    float v = 0.0f;

    const float2* inp = reinterpret_cast<const float2*>(inputs) + (size_t)b * TT;
    float* outp = out + (size_t)b * TT * NN + lane;

    int t = 0;
    while (t < TT) {
        const int chunk = min(32, TT - t);
        // Coalesced load of 32 timesteps of (hd, av); one sincos per lane.
        float chd = 0.f, shd = 0.f, av = 0.f;
        if (lane < chunk) {
            float2 x = inp[t + lane];
            sincosf(x.x, &shd, &chd);
            av = x.y;
        }
        #pragma unroll 4
        for (int j = 0; j < chunk; ++j) {
            const float cj = __shfl_sync(0xffffffffu, chd, j);
            const float sj = __shfl_sync(0xffffffffu, shd, j);
            const float aj = __shfl_sync(0xffffffffu, av,  j);

            const float m     = sqrtf(fmaf(u, u, v * v));
            const float decay = fmaf(-C1, m, C0);
            const float P = fmaf(kz, cj, fmaf(-C3 * aj, v, C2 * u));
            const float Q = fmaf(kz, sj, fmaf( C3 * aj, u, C2 * v));
            u = fmaf(decay, u, P);
            v = fmaf(decay, v, Q);

            // r_i = u*cos(phi_i) + v*sin(phi_i); three coalesced 32-lane waves
            outp[0]  = fmaf(v, s0, u * c0);
            outp[32] = fmaf(v, s1, u * c1);
            if (lane < NN - 64) outp[64] = fmaf(v, s2, u * c2);
            outp += NN;
        }
        t += chunk;
    }

    // r_final (1,B,N) appended after the (B,T,N) block
    const long long base = (long long)B * TT * NN;
    if (out_size >= base + (long long)B * NN) {
        float* fp = out + base + (size_t)b * NN + lane;
        fp[0]  = fmaf(v, s0, u * c0);
        fp[32] = fmaf(v, s1, u * c1);
        if (lane < NN - 64) fp[64] = fmaf(v, s2, u * c2);
    }
}

// --- host-side exact replica of the reference's _xi_inv (double precision) ---
static double xi_f(double a, double target)
{
    const double x = (a / 2.0) * (a / 2.0);
    double t0 = 1.0, t1 = a / 2.0;
    double i0 = t0, i1 = t1;
    for (int k = 1; k < 30; ++k) {
        t0 *= x / ((double)k * (double)k);
        t1 *= x / ((double)k * (double)(k + 1));
        i0 += t0;
        i1 += t1;
    }
    return a * i1 / i0 - target;
}

static float compute_kappa_z()
{
    const double target = 15.0 * 0.01;
    double lo = 1e-3, hi = 50.0;
    for (int i = 0; i < 200; ++i) {
        const double mid = 0.5 * (lo + hi);
        if (xi_f(lo, target) * xi_f(mid, target) <= 0.0) hi = mid;
        else lo = mid;
    }
    return (float)(0.5 * (lo + hi));
}

extern "C" void kernel_launch(void* const* d_in, const int* in_sizes, int n_in,
                              void* d_out, int out_size)
{
    const float* inputs = (const float*)d_in[0];  // (B,T,2)
    const float* phi    = (const float*)d_in[4];  // (N,)
    float* out = (float*)d_out;

    const int B = in_sizes[0] / (2 * TT);
    const float kz = compute_kappa_z();

    const int threads = 128;                   // 4 warps = 4 batches per block
    const int blocks = (B * 32 + threads - 1) / threads;
    ring_kernel<<<blocks, threads>>>(inputs, phi, out, B, kz, (long long)out_size);
}